// round 15
// baseline (speedup 1.0000x reference)
#include <cuda_runtime.h>
#include <cuda_bf16.h>
#include <cuda_fp16.h>
#include <cstdint>

#define NN   50000
#define NE   800000
#define ETOT (NE + NN)   // edges + self loops
#define IN   128
#define C1   256         // HEADS*HIDDEN
#define H1   4
#define F1   64
#define C2   32
#define SCAN_B 512
#define NB   ((NN + SCAN_B - 1) / SCAN_B)   // 98

// ---------------- scratch (static device globals; no allocation) ----------------
__device__ __half2  g_h1h[NN * 128];   // layer1 features, fp16x2 (gather-only payload)
__device__ float    g_act[NN * C1];
__device__ float    g_h2 [NN * C2];
__device__ float    g_as1[NN * H1];
__device__ float    g_ad1[NN * H1];
__device__ float    g_as2[NN];
__device__ float    g_ad2[NN];
__device__ unsigned g_gm1u[4];
__device__ unsigned g_gm2u;
__device__ int      g_deg[NN];
__device__ int      g_off[NN + 1];
__device__ int      g_pos[NN];
__device__ int      g_bsum[128];
__device__ int      g_csr[ETOT];
__device__ int      g_stride;

__device__ __forceinline__ float lrelu(float v) { return v > 0.f ? v : 0.2f * v; }

__device__ __forceinline__ unsigned encf(float f) {
    unsigned u = __float_as_uint(f);
    return (u & 0x80000000u) ? ~u : (u | 0x80000000u);
}
__device__ __forceinline__ float decf(unsigned e) {
    return (e & 0x80000000u) ? __uint_as_float(e ^ 0x80000000u) : __uint_as_float(~e);
}

// packed fp32x2 helpers (FFMA2)
__device__ __forceinline__ unsigned long long dup2(float v) {
    unsigned long long r;
    asm("mov.b64 %0, {%1, %1};" : "=l"(r) : "f"(v));
    return r;
}
__device__ __forceinline__ unsigned long long fma2(unsigned long long a,
                                                   unsigned long long b,
                                                   unsigned long long c) {
    unsigned long long d;
    asm("fma.rn.f32x2 %0, %1, %2, %3;" : "=l"(d) : "l"(a), "l"(b), "l"(c));
    return d;
}
__device__ __forceinline__ void unpack2(unsigned long long v, float& lo, float& hi) {
    asm("mov.b64 {%0, %1}, %2;" : "=f"(lo), "=f"(hi) : "l"(v));
}

__device__ __forceinline__ uint32_t s2u(const void* p) {
    return (uint32_t)__cvta_generic_to_shared(p);
}

// ---------------- zero + edge_index dtype detection (block 0) ----------------
__global__ void k_zero_deg(const int* __restrict__ p) {
    int i = blockIdx.x * blockDim.x + threadIdx.x;
    if (i < NN) g_deg[i] = 0;
    if (i < 4)  g_gm1u[i] = 0u;
    if (i == 4) g_gm2u = 0u;
    if (blockIdx.x == 0) {
        __shared__ int nz[256];
        int t = threadIdx.x;
        int acc = 0;
#pragma unroll
        for (int j = 0; j < 4; j++) acc |= p[2 * (t + 256 * j) + 1];
        nz[t] = acc;
        __syncthreads();
        for (int st = 128; st > 0; st >>= 1) {
            if (t < st) nz[t] |= nz[t + st];
            __syncthreads();
        }
        if (t == 0) g_stride = (nz[0] == 0) ? 2 : 1;
    }
}

// ---------------- CSR build ----------------
__global__ void k_count(const int* __restrict__ ei) {
    int e = blockIdx.x * blockDim.x + threadIdx.x;
    if (e >= ETOT) return;
    int st = g_stride;
    int d = (e < NE) ? ei[(NE + e) * st] : (e - NE);
    atomicAdd(&g_deg[d], 1);
}

__global__ void k_scan_local() {
    __shared__ int s[SCAN_B];
    int i = blockIdx.x * SCAN_B + threadIdx.x;
    int v = (i < NN) ? g_deg[i] : 0;
    s[threadIdx.x] = v;
    __syncthreads();
    for (int st = 1; st < SCAN_B; st <<= 1) {
        int t = (threadIdx.x >= st) ? s[threadIdx.x - st] : 0;
        __syncthreads();
        s[threadIdx.x] += t;
        __syncthreads();
    }
    if (i < NN) g_off[i] = s[threadIdx.x] - v;
    if (threadIdx.x == SCAN_B - 1) g_bsum[blockIdx.x] = s[SCAN_B - 1];
}

// merged bsum+add: each block scans the 98 block sums locally (cheap, smem),
// then applies its own exclusive offset. Stays fully parallel across blocks.
__global__ void k_scan_add() {
    __shared__ int sb[128];
    int tid = threadIdx.x;
    if (tid < 128) sb[tid] = (tid < NB) ? g_bsum[tid] : 0;
    __syncthreads();
    for (int st = 1; st < 128; st <<= 1) {
        int t = (tid < 128 && tid >= st) ? sb[tid - st] : 0;
        __syncthreads();
        if (tid < 128) sb[tid] += t;
        __syncthreads();
    }
    int boff = (blockIdx.x == 0) ? 0 : sb[blockIdx.x - 1];
    int i = blockIdx.x * SCAN_B + tid;
    if (i < NN) {
        int o = g_off[i] + boff;
        g_off[i] = o;
        g_pos[i] = o;
    }
    if (i == 0) g_off[NN] = ETOT;
}

__global__ void k_fill(const int* __restrict__ ei) {
    int e = blockIdx.x * blockDim.x + threadIdx.x;
    if (e >= ETOT) return;
    int st = g_stride;
    int s, d;
    if (e < NE) { s = ei[e * st]; d = ei[(NE + e) * st]; }
    else        { s = d = e - NE; }
    int slot = atomicAdd(&g_pos[d], 1);
    g_csr[slot] = s;
}

// ---------------- GEMM1 (HMMA) + alpha1 + global-max fused; W1 cvt inline ----------------
__global__ void __launch_bounds__(256) k_gemm1(const float* __restrict__ x,
                                               const float* __restrict__ W1,
                                               const float* __restrict__ av_s,
                                               const float* __restrict__ av_d) {
    __shared__ __half xh[32][136];    // 272B row stride (conflict-free ldmatrix)
    __shared__ __half wh[128][136];
    __shared__ float  smx[32];
    float* st = (float*)&xh[0][0];    // 32KB staging overlays xh+wh after mainloop

    int m0 = blockIdx.x * 32;
    int tid = threadIdx.x;
    int warp = tid >> 5, lane = tid & 31;

    // x tile -> fp16 smem (vectorized)
#pragma unroll
    for (int it = 0; it < 2; it++) {
        int e = (it * 256 + tid) * 8;
        int i = e >> 7, k = e & 127;
        float4 v0, v1;
        if (m0 + i < NN) {
            v0 = *(const float4*)&x[(m0 + i) * IN + k];
            v1 = *(const float4*)&x[(m0 + i) * IN + k + 4];
        } else {
            v0 = make_float4(0.f, 0.f, 0.f, 0.f);
            v1 = v0;
        }
        __half2 h0 = __floats2half2_rn(v0.x, v0.y);
        __half2 h1 = __floats2half2_rn(v0.z, v0.w);
        __half2 h2 = __floats2half2_rn(v1.x, v1.y);
        __half2 h3 = __floats2half2_rn(v1.z, v1.w);
        uint4 pk;
        pk.x = *(unsigned*)&h0; pk.y = *(unsigned*)&h1;
        pk.z = *(unsigned*)&h2; pk.w = *(unsigned*)&h3;
        *(uint4*)&xh[i][k] = pk;
    }

    float d[2][2][2][4];
#pragma unroll
    for (int h = 0; h < 2; h++)
#pragma unroll
        for (int mt = 0; mt < 2; mt++)
#pragma unroll
            for (int nt = 0; nt < 2; nt++)
#pragma unroll
                for (int q = 0; q < 4; q++) d[h][mt][nt][q] = 0.f;

    for (int h = 0; h < 2; h++) {
        __syncthreads();
        // wh <- fp16(W1[k][h*128 + nl]) — converted inline (no cvt kernel)
#pragma unroll
        for (int it = 0; it < 8; it++) {
            int e = (it * 256 + tid) * 8;
            int k = e >> 7, nl = e & 127;
            float4 a = *(const float4*)&W1[k * C1 + h * 128 + nl];
            float4 b = *(const float4*)&W1[k * C1 + h * 128 + nl + 4];
            __half2 h0 = __floats2half2_rn(a.x, a.y);
            __half2 h1 = __floats2half2_rn(a.z, a.w);
            __half2 h2 = __floats2half2_rn(b.x, b.y);
            __half2 h3 = __floats2half2_rn(b.z, b.w);
            uint4 pk;
            pk.x = *(unsigned*)&h0; pk.y = *(unsigned*)&h1;
            pk.z = *(unsigned*)&h2; pk.w = *(unsigned*)&h3;
            *(uint4*)&wh[k][nl] = pk;
        }
        __syncthreads();

#pragma unroll
        for (int ks = 0; ks < 8; ks++) {
            uint32_t a[2][4];
#pragma unroll
            for (int mt = 0; mt < 2; mt++) {
                uint32_t addr = s2u(&xh[mt * 16 + (lane & 15)][ks * 16 + (lane >> 4) * 8]);
                asm volatile("ldmatrix.sync.aligned.m8n8.x4.shared.b16 {%0,%1,%2,%3}, [%4];"
                             : "=r"(a[mt][0]), "=r"(a[mt][1]), "=r"(a[mt][2]), "=r"(a[mt][3])
                             : "r"(addr));
            }
#pragma unroll
            for (int nt = 0; nt < 2; nt++) {
                uint32_t b0, b1;
                uint32_t baddr = s2u(&wh[ks * 16 + (lane & 15)][warp * 16 + nt * 8]);
                asm volatile("ldmatrix.sync.aligned.m8n8.x2.trans.shared.b16 {%0,%1}, [%2];"
                             : "=r"(b0), "=r"(b1) : "r"(baddr));
#pragma unroll
                for (int mt = 0; mt < 2; mt++) {
                    asm volatile(
                        "mma.sync.aligned.m16n8k16.row.col.f32.f16.f16.f32 "
                        "{%0,%1,%2,%3}, {%4,%5,%6,%7}, {%8,%9}, {%0,%1,%2,%3};"
                        : "+f"(d[h][mt][nt][0]), "+f"(d[h][mt][nt][1]),
                          "+f"(d[h][mt][nt][2]), "+f"(d[h][mt][nt][3])
                        : "r"(a[mt][0]), "r"(a[mt][1]), "r"(a[mt][2]), "r"(a[mt][3]),
                          "r"(b0), "r"(b1));
                }
            }
        }
    }
    __syncthreads();

    // D fragments -> fp32 staging st[row*256 + col]
#pragma unroll
    for (int h = 0; h < 2; h++)
#pragma unroll
        for (int mt = 0; mt < 2; mt++)
#pragma unroll
            for (int nt = 0; nt < 2; nt++) {
                int row = mt * 16 + (lane >> 2);
                int col = h * 128 + warp * 16 + nt * 8 + (lane & 3) * 2;
                *(float2*)&st[row * 256 + col] =
                    make_float2(d[h][mt][nt][0], d[h][mt][nt][1]);
                *(float2*)&st[(row + 8) * 256 + col] =
                    make_float2(d[h][mt][nt][2], d[h][mt][nt][3]);
            }
    __syncthreads();

    // coalesced fp16 store of h1
#pragma unroll
    for (int r = 0; r < 8; r++) {
        int idx = r * 256 + tid;
        int node = idx >> 6, q = idx & 63;
        if (m0 + node < NN) {
            float4 v = *(float4*)&st[node * 256 + 4 * q];
            __half2 h01 = __floats2half2_rn(v.x, v.y);
            __half2 h23 = __floats2half2_rn(v.z, v.w);
            uint2 pk;
            pk.x = *(unsigned*)&h01;
            pk.y = *(unsigned*)&h23;
            *(uint2*)&g_h1h[(m0 + node) * 128 + 2 * q] = pk;
        }
    }

    // alpha epilogue: warp w handles nodes w + 8r
    float a_s[8], a_d[8];
#pragma unroll
    for (int j = 0; j < 8; j++) {
        a_s[j] = av_s[lane + 32 * j];
        a_d[j] = av_d[lane + 32 * j];
    }
    float mx[4] = {-1e30f, -1e30f, -1e30f, -1e30f};
#pragma unroll
    for (int r = 0; r < 4; r++) {
        int i = warp + 8 * r;
        float ps[4] = {0.f, 0.f, 0.f, 0.f};
        float pd[4] = {0.f, 0.f, 0.f, 0.f};
#pragma unroll
        for (int j = 0; j < 8; j++) {
            float v = st[i * 256 + lane + 32 * j];
            int h = j >> 1;
            ps[h] = fmaf(v, a_s[j], ps[h]);
            pd[h] = fmaf(v, a_d[j], pd[h]);
        }
#pragma unroll
        for (int o = 16; o > 0; o >>= 1) {
#pragma unroll
            for (int h = 0; h < 4; h++) {
                ps[h] += __shfl_down_sync(0xffffffffu, ps[h], o);
                pd[h] += __shfl_down_sync(0xffffffffu, pd[h], o);
            }
        }
        if (lane == 0 && m0 + i < NN) {
#pragma unroll
            for (int h = 0; h < 4; h++) {
                g_as1[(m0 + i) * 4 + h] = ps[h];
                g_ad1[(m0 + i) * 4 + h] = pd[h];
                mx[h] = fmaxf(mx[h], ps[h]);
            }
        }
    }
    if (lane == 0) {
#pragma unroll
        for (int h = 0; h < 4; h++) smx[warp * 4 + h] = mx[h];
    }
    __syncthreads();
    if (tid < 4) {
        float m = -1e30f;
#pragma unroll
        for (int w = 0; w < 8; w++) m = fmaxf(m, smx[w * 4 + tid]);
        if (m > -1e29f) atomicMax(&g_gm1u[tid], encf(m));
    }
}

// ---------------- agg1: WARP per node, inline softmax weights ----------------
__global__ void __launch_bounds__(256) k_agg1(const float* __restrict__ b1) {
    int warp = threadIdx.x >> 5;
    int n = blockIdx.x * 8 + warp;
    if (n >= NN) return;
    int lane = threadIdx.x & 31;
    int off = g_off[n];
    int deg = g_off[n + 1] - off;
    int hf  = lane >> 3;

    float adh = g_ad1[n * 4 + hf];
    float Bh  = lrelu(decf(g_gm1u[hf]) + adh);

    float acc[8];
#pragma unroll
    for (int q = 0; q < 8; q++) acc[q] = 0.f;
    float wsum = 0.f;

    int j = 0;
    for (; j + 3 < deg; j += 4) {
        int s0 = g_csr[off + j],     s1 = g_csr[off + j + 1];
        int s2 = g_csr[off + j + 2], s3 = g_csr[off + j + 3];
        float w0 = __expf(lrelu(g_as1[s0 * 4 + hf] + adh) - Bh);
        float w1 = __expf(lrelu(g_as1[s1 * 4 + hf] + adh) - Bh);
        float w2 = __expf(lrelu(g_as1[s2 * 4 + hf] + adh) - Bh);
        float w3 = __expf(lrelu(g_as1[s3 * 4 + hf] + adh) - Bh);
        uint4 p0 = __ldcg((const uint4*)&g_h1h[s0 * 128 + lane * 4]);
        uint4 p1 = __ldcg((const uint4*)&g_h1h[s1 * 128 + lane * 4]);
        uint4 p2 = __ldcg((const uint4*)&g_h1h[s2 * 128 + lane * 4]);
        uint4 p3 = __ldcg((const uint4*)&g_h1h[s3 * 128 + lane * 4]);
        wsum += w0 + w1 + w2 + w3;
#pragma unroll
        for (int h2i = 0; h2i < 4; h2i++) {
            float2 f0 = __half22float2(((const __half2*)&p0)[h2i]);
            float2 f1 = __half22float2(((const __half2*)&p1)[h2i]);
            float2 f2 = __half22float2(((const __half2*)&p2)[h2i]);
            float2 f3 = __half22float2(((const __half2*)&p3)[h2i]);
            acc[2 * h2i]     = fmaf(f0.x, w0, acc[2 * h2i]);
            acc[2 * h2i + 1] = fmaf(f0.y, w0, acc[2 * h2i + 1]);
            acc[2 * h2i]     = fmaf(f1.x, w1, acc[2 * h2i]);
            acc[2 * h2i + 1] = fmaf(f1.y, w1, acc[2 * h2i + 1]);
            acc[2 * h2i]     = fmaf(f2.x, w2, acc[2 * h2i]);
            acc[2 * h2i + 1] = fmaf(f2.y, w2, acc[2 * h2i + 1]);
            acc[2 * h2i]     = fmaf(f3.x, w3, acc[2 * h2i]);
            acc[2 * h2i + 1] = fmaf(f3.y, w3, acc[2 * h2i + 1]);
        }
    }
    for (; j < deg; j++) {
        int s = g_csr[off + j];
        float w = __expf(lrelu(g_as1[s * 4 + hf] + adh) - Bh);
        uint4 p = __ldcg((const uint4*)&g_h1h[s * 128 + lane * 4]);
        wsum += w;
#pragma unroll
        for (int h2i = 0; h2i < 4; h2i++) {
            float2 f = __half22float2(((const __half2*)&p)[h2i]);
            acc[2 * h2i]     = fmaf(f.x, w, acc[2 * h2i]);
            acc[2 * h2i + 1] = fmaf(f.y, w, acc[2 * h2i + 1]);
        }
    }

    float denom = wsum + 1e-16f;
    float4 bb0 = *(const float4*)&b1[lane * 8];
    float4 bb1 = *(const float4*)&b1[lane * 8 + 4];
    float o0 = acc[0] / denom + bb0.x;
    float o1 = acc[1] / denom + bb0.y;
    float o2 = acc[2] / denom + bb0.z;
    float o3 = acc[3] / denom + bb0.w;
    float o4 = acc[4] / denom + bb1.x;
    float o5 = acc[5] / denom + bb1.y;
    float o6 = acc[6] / denom + bb1.z;
    float o7 = acc[7] / denom + bb1.w;
    o0 = (o0 > 0.f) ? o0 : expm1f(o0);
    o1 = (o1 > 0.f) ? o1 : expm1f(o1);
    o2 = (o2 > 0.f) ? o2 : expm1f(o2);
    o3 = (o3 > 0.f) ? o3 : expm1f(o3);
    o4 = (o4 > 0.f) ? o4 : expm1f(o4);
    o5 = (o5 > 0.f) ? o5 : expm1f(o5);
    o6 = (o6 > 0.f) ? o6 : expm1f(o6);
    o7 = (o7 > 0.f) ? o7 : expm1f(o7);
    *(float4*)&g_act[n * C1 + lane * 8]     = make_float4(o0, o1, o2, o3);
    *(float4*)&g_act[n * C1 + lane * 8 + 4] = make_float4(o4, o5, o6, o7);
}

// ---------------- GEMM2 + alpha2 + global-max fused (FFMA2 core) ----------------
__global__ void __launch_bounds__(256) k_gemm2(const float* __restrict__ W2,
                                               const float* __restrict__ av_s,
                                               const float* __restrict__ av_d) {
    __shared__ float sx[C1 * 32];
    __shared__ float sm8[8];
    int m0 = blockIdx.x * 32;
    int tid = threadIdx.x;
    for (int idx = tid; idx < 32 * C1; idx += 256) {
        int i = idx / C1, k = idx % C1;
        sx[k * 32 + i] = (m0 + i < NN) ? g_act[(m0 + i) * C1 + k] : 0.f;
    }
    __syncthreads();
    int col = tid & 31, ir = tid >> 5;
    unsigned long long acc01 = 0ull, acc23 = 0ull;
#pragma unroll 4
    for (int k = 0; k < C1; k++) {
        unsigned long long wd = dup2(W2[k * C2 + col]);
        unsigned long long x01 =
            *reinterpret_cast<const unsigned long long*>(&sx[k * 32 + ir * 4]);
        unsigned long long x23 =
            *reinterpret_cast<const unsigned long long*>(&sx[k * 32 + ir * 4 + 2]);
        acc01 = fma2(x01, wd, acc01);
        acc23 = fma2(x23, wd, acc23);
    }
    float acc[4];
    unpack2(acc01, acc[0], acc[1]);
    unpack2(acc23, acc[2], acc[3]);

    float s_l = av_s[col], d_l = av_d[col];
    float mx = -1e30f;
#pragma unroll
    for (int j = 0; j < 4; j++) {
        int node = m0 + ir * 4 + j;
        if (node < NN) g_h2[node * C2 + col] = acc[j];
        float ss = acc[j] * s_l, sd = acc[j] * d_l;
#pragma unroll
        for (int o = 16; o > 0; o >>= 1) {
            ss += __shfl_down_sync(0xffffffffu, ss, o);
            sd += __shfl_down_sync(0xffffffffu, sd, o);
        }
        if (col == 0 && node < NN) {
            g_as2[node] = ss;
            g_ad2[node] = sd;
            mx = fmaxf(mx, ss);
        }
    }
    if (col == 0) sm8[ir] = mx;
    __syncthreads();
    if (tid == 0) {
        float m = -1e30f;
#pragma unroll
        for (int w = 0; w < 8; w++) m = fmaxf(m, sm8[w]);
        if (m > -1e29f) atomicMax(&g_gm2u, encf(m));
    }
}

// ---------------- agg2: warp per dst node, single pass, 4-way MLP ----------------
__global__ void k_agg2(const float* __restrict__ b2, float* __restrict__ out) {
    int warp = threadIdx.x >> 5;
    int n = blockIdx.x * 8 + warp;
    if (n >= NN) return;
    int lane = threadIdx.x & 31;
    int off = g_off[n], deg = g_off[n + 1] - off;
    float adn = g_ad2[n];
    float B = lrelu(decf(g_gm2u) + adn);

    float a0 = 0.f, a1 = 0.f, a2 = 0.f, a3 = 0.f;
    float w0s = 0.f, w1s = 0.f, w2s = 0.f, w3s = 0.f;
    int i = 0;
    for (; i + 3 < deg; i += 4) {
        int s0 = g_csr[off + i],     s1 = g_csr[off + i + 1];
        int s2 = g_csr[off + i + 2], s3 = g_csr[off + i + 3];
        float w0 = __expf(lrelu(g_as2[s0] + adn) - B);
        float w1 = __expf(lrelu(g_as2[s1] + adn) - B);
        float w2 = __expf(lrelu(g_as2[s2] + adn) - B);
        float w3 = __expf(lrelu(g_as2[s3] + adn) - B);
        a0 = fmaf(__ldcg(&g_h2[s0 * C2 + lane]), w0, a0);
        a1 = fmaf(__ldcg(&g_h2[s1 * C2 + lane]), w1, a1);
        a2 = fmaf(__ldcg(&g_h2[s2 * C2 + lane]), w2, a2);
        a3 = fmaf(__ldcg(&g_h2[s3 * C2 + lane]), w3, a3);
        w0s += w0; w1s += w1; w2s += w2; w3s += w3;
    }
    for (; i < deg; i++) {
        int s = g_csr[off + i];
        float w = __expf(lrelu(g_as2[s] + adn) - B);
        a0 = fmaf(__ldcg(&g_h2[s * C2 + lane]), w, a0);
        w0s += w;
    }
    out[n * C2 + lane] = (a0 + a1 + a2 + a3) / (w0s + w1s + w2s + w3s + 1e-16f) + b2[lane];
}

// ---------------- launch: CSR build (stream 0) ∥ GEMM1 (side stream) ----------------
extern "C" void kernel_launch(void* const* d_in, const int* in_sizes, int n_in,
                              void* d_out, int out_size) {
    const float* x    = (const float*)d_in[0];
    const int*   ei   = (const int*)d_in[1];
    const float* W1   = (const float*)d_in[2];
    const float* as1v = (const float*)d_in[3];
    const float* ad1v = (const float*)d_in[4];
    const float* b1   = (const float*)d_in[5];
    const float* W2   = (const float*)d_in[6];
    const float* as2v = (const float*)d_in[7];
    const float* ad2v = (const float*)d_in[8];
    const float* b2   = (const float*)d_in[9];
    float*       out  = (float*)d_out;

    cudaStream_t s2;
    cudaStreamCreateWithFlags(&s2, cudaStreamNonBlocking);
    cudaEvent_t eRoot, eG1;
    cudaEventCreateWithFlags(&eRoot, cudaEventDisableTiming);
    cudaEventCreateWithFlags(&eG1, cudaEventDisableTiming);

    cudaEventRecord(eRoot, 0);
    cudaStreamWaitEvent(s2, eRoot, 0);
    k_gemm1<<<(NN + 31) / 32, 256, 0, s2>>>(x, W1, as1v, ad1v);
    cudaEventRecord(eG1, s2);

    // CSR chain on the main stream (scan = 2 kernels now)
    k_zero_deg<<<(NN + 255) / 256, 256>>>(ei);
    k_count<<<(ETOT + 255) / 256, 256>>>(ei);
    k_scan_local<<<NB, SCAN_B>>>();
    k_scan_add<<<NB, SCAN_B>>>();
    k_fill<<<(ETOT + 255) / 256, 256>>>(ei);

    // join, then the dependent chain
    cudaStreamWaitEvent(0, eG1, 0);
    k_agg1<<<(NN + 7) / 8, 256>>>(b1);
    k_gemm2<<<(NN + 31) / 32, 256>>>(W2, as2v, ad2v);
    k_agg2<<<(NN + 7) / 8, 256>>>(b2, out);
    // s2 / events intentionally leaked (host handles only)
}

// round 16
// speedup vs baseline: 1.0507x; 1.0507x over previous
#include <cuda_runtime.h>
#include <cuda_bf16.h>
#include <cuda_fp16.h>
#include <cstdint>

#define NN   50000
#define NE   800000
#define ETOT (NE + NN)   // edges + self loops
#define IN   128
#define C1   256         // HEADS*HIDDEN
#define H1   4
#define F1   64
#define C2   32
#define SCAN_B 512
#define NB   ((NN + SCAN_B - 1) / SCAN_B)   // 98

// ---------------- scratch (static device globals; no allocation) ----------------
__device__ __half2  g_h1h[NN * 128];   // layer1 features, fp16x2 (gather-only payload)
__device__ __half   g_W1h[IN * C1];    // fp16 W1 (converted once)
__device__ float    g_act[NN * C1];
__device__ float    g_h2 [NN * C2];
__device__ float    g_as1[NN * H1];
__device__ float    g_ad1[NN * H1];
__device__ float    g_as2[NN];
__device__ float    g_ad2[NN];
__device__ unsigned g_gm1u[4];
__device__ unsigned g_gm2u;
__device__ int      g_deg[NN];
__device__ int      g_off[NN + 1];
__device__ int      g_pos[NN];
__device__ int      g_bsum[128];
__device__ int      g_boff[128];
__device__ int      g_csr[ETOT];
__device__ int      g_stride;

__device__ __forceinline__ float lrelu(float v) { return v > 0.f ? v : 0.2f * v; }

__device__ __forceinline__ unsigned encf(float f) {
    unsigned u = __float_as_uint(f);
    return (u & 0x80000000u) ? ~u : (u | 0x80000000u);
}
__device__ __forceinline__ float decf(unsigned e) {
    return (e & 0x80000000u) ? __uint_as_float(e ^ 0x80000000u) : __uint_as_float(~e);
}

// packed fp32x2 helpers (FFMA2)
__device__ __forceinline__ unsigned long long dup2(float v) {
    unsigned long long r;
    asm("mov.b64 %0, {%1, %1};" : "=l"(r) : "f"(v));
    return r;
}
__device__ __forceinline__ unsigned long long fma2(unsigned long long a,
                                                   unsigned long long b,
                                                   unsigned long long c) {
    unsigned long long d;
    asm("fma.rn.f32x2 %0, %1, %2, %3;" : "=l"(d) : "l"(a), "l"(b), "l"(c));
    return d;
}
__device__ __forceinline__ void unpack2(unsigned long long v, float& lo, float& hi) {
    asm("mov.b64 {%0, %1}, %2;" : "=f"(lo), "=f"(hi) : "l"(v));
}

__device__ __forceinline__ uint32_t s2u(const void* p) {
    return (uint32_t)__cvta_generic_to_shared(p);
}

// ---------------- zero + edge_index dtype detection (block 0) ----------------
__global__ void k_zero_deg(const int* __restrict__ p) {
    int i = blockIdx.x * blockDim.x + threadIdx.x;
    if (i < NN) g_deg[i] = 0;
    if (i < 4)  g_gm1u[i] = 0u;
    if (i == 4) g_gm2u = 0u;
    if (blockIdx.x == 0) {
        __shared__ int nz[256];
        int t = threadIdx.x;
        int acc = 0;
#pragma unroll
        for (int j = 0; j < 4; j++) acc |= p[2 * (t + 256 * j) + 1];
        nz[t] = acc;
        __syncthreads();
        for (int st = 128; st > 0; st >>= 1) {
            if (t < st) nz[t] |= nz[t + st];
            __syncthreads();
        }
        if (t == 0) g_stride = (nz[0] == 0) ? 2 : 1;
    }
}

// ---------------- CSR build ----------------
__global__ void k_count(const int* __restrict__ ei) {
    int e = blockIdx.x * blockDim.x + threadIdx.x;
    if (e >= ETOT) return;
    int st = g_stride;
    int d = (e < NE) ? ei[(NE + e) * st] : (e - NE);
    atomicAdd(&g_deg[d], 1);
}

__global__ void k_scan_local() {
    __shared__ int s[SCAN_B];
    int i = blockIdx.x * SCAN_B + threadIdx.x;
    int v = (i < NN) ? g_deg[i] : 0;
    s[threadIdx.x] = v;
    __syncthreads();
    for (int st = 1; st < SCAN_B; st <<= 1) {
        int t = (threadIdx.x >= st) ? s[threadIdx.x - st] : 0;
        __syncthreads();
        s[threadIdx.x] += t;
        __syncthreads();
    }
    if (i < NN) g_off[i] = s[threadIdx.x] - v;
    if (threadIdx.x == SCAN_B - 1) g_bsum[blockIdx.x] = s[SCAN_B - 1];
}

__global__ void k_scan_bsum() {
    __shared__ int s[128];
    int v = (threadIdx.x < NB) ? g_bsum[threadIdx.x] : 0;
    s[threadIdx.x] = v;
    __syncthreads();
    for (int st = 1; st < 128; st <<= 1) {
        int t = (threadIdx.x >= st) ? s[threadIdx.x - st] : 0;
        __syncthreads();
        s[threadIdx.x] += t;
        __syncthreads();
    }
    if (threadIdx.x < NB) g_boff[threadIdx.x] = s[threadIdx.x] - v;
}

__global__ void k_scan_add() {
    int i = blockIdx.x * SCAN_B + threadIdx.x;
    if (i < NN) {
        int o = g_off[i] + g_boff[blockIdx.x];
        g_off[i] = o;
        g_pos[i] = o;
    }
    if (i == 0) g_off[NN] = ETOT;
}

__global__ void k_fill(const int* __restrict__ ei) {
    int e = blockIdx.x * blockDim.x + threadIdx.x;
    if (e >= ETOT) return;
    int st = g_stride;
    int s, d;
    if (e < NE) { s = ei[e * st]; d = ei[(NE + e) * st]; }
    else        { s = d = e - NE; }
    int slot = atomicAdd(&g_pos[d], 1);
    g_csr[slot] = s;
}

// ---------------- W1 -> fp16 (once, on side stream before gemm1) ----------------
__global__ void k_cvtW1(const float* __restrict__ W1) {
    int i = blockIdx.x * 256 + threadIdx.x;
    if (i < IN * C1) g_W1h[i] = __float2half(W1[i]);
}

// ---------------- GEMM1 (HMMA) + alpha1 + global-max fused ----------------
__global__ void __launch_bounds__(256) k_gemm1(const float* __restrict__ x,
                                               const float* __restrict__ av_s,
                                               const float* __restrict__ av_d) {
    __shared__ __half xh[32][136];    // 272B row stride (conflict-free ldmatrix)
    __shared__ __half wh[128][136];
    __shared__ float  smx[32];
    float* st = (float*)&xh[0][0];    // 32KB staging overlays xh+wh after mainloop

    int m0 = blockIdx.x * 32;
    int tid = threadIdx.x;
    int warp = tid >> 5, lane = tid & 31;

    // x tile -> fp16 smem (vectorized)
#pragma unroll
    for (int it = 0; it < 2; it++) {
        int e = (it * 256 + tid) * 8;
        int i = e >> 7, k = e & 127;
        float4 v0, v1;
        if (m0 + i < NN) {
            v0 = *(const float4*)&x[(m0 + i) * IN + k];
            v1 = *(const float4*)&x[(m0 + i) * IN + k + 4];
        } else {
            v0 = make_float4(0.f, 0.f, 0.f, 0.f);
            v1 = v0;
        }
        __half2 h0 = __floats2half2_rn(v0.x, v0.y);
        __half2 h1 = __floats2half2_rn(v0.z, v0.w);
        __half2 h2 = __floats2half2_rn(v1.x, v1.y);
        __half2 h3 = __floats2half2_rn(v1.z, v1.w);
        uint4 pk;
        pk.x = *(unsigned*)&h0; pk.y = *(unsigned*)&h1;
        pk.z = *(unsigned*)&h2; pk.w = *(unsigned*)&h3;
        *(uint4*)&xh[i][k] = pk;
    }

    float d[2][2][2][4];
#pragma unroll
    for (int h = 0; h < 2; h++)
#pragma unroll
        for (int mt = 0; mt < 2; mt++)
#pragma unroll
            for (int nt = 0; nt < 2; nt++)
#pragma unroll
                for (int q = 0; q < 4; q++) d[h][mt][nt][q] = 0.f;

    for (int h = 0; h < 2; h++) {
        __syncthreads();
#pragma unroll
        for (int it = 0; it < 8; it++) {
            int e = (it * 256 + tid) * 8;
            int k = e >> 7, nl = e & 127;
            *(uint4*)&wh[k][nl] = *(const uint4*)&g_W1h[k * C1 + h * 128 + nl];
        }
        __syncthreads();

#pragma unroll
        for (int ks = 0; ks < 8; ks++) {
            uint32_t a[2][4];
#pragma unroll
            for (int mt = 0; mt < 2; mt++) {
                uint32_t addr = s2u(&xh[mt * 16 + (lane & 15)][ks * 16 + (lane >> 4) * 8]);
                asm volatile("ldmatrix.sync.aligned.m8n8.x4.shared.b16 {%0,%1,%2,%3}, [%4];"
                             : "=r"(a[mt][0]), "=r"(a[mt][1]), "=r"(a[mt][2]), "=r"(a[mt][3])
                             : "r"(addr));
            }
#pragma unroll
            for (int nt = 0; nt < 2; nt++) {
                uint32_t b0, b1;
                uint32_t baddr = s2u(&wh[ks * 16 + (lane & 15)][warp * 16 + nt * 8]);
                asm volatile("ldmatrix.sync.aligned.m8n8.x2.trans.shared.b16 {%0,%1}, [%2];"
                             : "=r"(b0), "=r"(b1) : "r"(baddr));
#pragma unroll
                for (int mt = 0; mt < 2; mt++) {
                    asm volatile(
                        "mma.sync.aligned.m16n8k16.row.col.f32.f16.f16.f32 "
                        "{%0,%1,%2,%3}, {%4,%5,%6,%7}, {%8,%9}, {%0,%1,%2,%3};"
                        : "+f"(d[h][mt][nt][0]), "+f"(d[h][mt][nt][1]),
                          "+f"(d[h][mt][nt][2]), "+f"(d[h][mt][nt][3])
                        : "r"(a[mt][0]), "r"(a[mt][1]), "r"(a[mt][2]), "r"(a[mt][3]),
                          "r"(b0), "r"(b1));
                }
            }
        }
    }
    __syncthreads();

    // D fragments -> fp32 staging st[row*256 + col]
#pragma unroll
    for (int h = 0; h < 2; h++)
#pragma unroll
        for (int mt = 0; mt < 2; mt++)
#pragma unroll
            for (int nt = 0; nt < 2; nt++) {
                int row = mt * 16 + (lane >> 2);
                int col = h * 128 + warp * 16 + nt * 8 + (lane & 3) * 2;
                *(float2*)&st[row * 256 + col] =
                    make_float2(d[h][mt][nt][0], d[h][mt][nt][1]);
                *(float2*)&st[(row + 8) * 256 + col] =
                    make_float2(d[h][mt][nt][2], d[h][mt][nt][3]);
            }
    __syncthreads();

    // coalesced fp16 store of h1
#pragma unroll
    for (int r = 0; r < 8; r++) {
        int idx = r * 256 + tid;
        int node = idx >> 6, q = idx & 63;
        if (m0 + node < NN) {
            float4 v = *(float4*)&st[node * 256 + 4 * q];
            __half2 h01 = __floats2half2_rn(v.x, v.y);
            __half2 h23 = __floats2half2_rn(v.z, v.w);
            uint2 pk;
            pk.x = *(unsigned*)&h01;
            pk.y = *(unsigned*)&h23;
            *(uint2*)&g_h1h[(m0 + node) * 128 + 2 * q] = pk;
        }
    }

    // alpha epilogue
    float a_s[8], a_d[8];
#pragma unroll
    for (int j = 0; j < 8; j++) {
        a_s[j] = av_s[lane + 32 * j];
        a_d[j] = av_d[lane + 32 * j];
    }
    float mx[4] = {-1e30f, -1e30f, -1e30f, -1e30f};
#pragma unroll
    for (int r = 0; r < 4; r++) {
        int i = warp + 8 * r;
        float ps[4] = {0.f, 0.f, 0.f, 0.f};
        float pd[4] = {0.f, 0.f, 0.f, 0.f};
#pragma unroll
        for (int j = 0; j < 8; j++) {
            float v = st[i * 256 + lane + 32 * j];
            int h = j >> 1;
            ps[h] = fmaf(v, a_s[j], ps[h]);
            pd[h] = fmaf(v, a_d[j], pd[h]);
        }
#pragma unroll
        for (int o = 16; o > 0; o >>= 1) {
#pragma unroll
            for (int h = 0; h < 4; h++) {
                ps[h] += __shfl_down_sync(0xffffffffu, ps[h], o);
                pd[h] += __shfl_down_sync(0xffffffffu, pd[h], o);
            }
        }
        if (lane == 0 && m0 + i < NN) {
#pragma unroll
            for (int h = 0; h < 4; h++) {
                g_as1[(m0 + i) * 4 + h] = ps[h];
                g_ad1[(m0 + i) * 4 + h] = pd[h];
                mx[h] = fmaxf(mx[h], ps[h]);
            }
        }
    }
    if (lane == 0) {
#pragma unroll
        for (int h = 0; h < 4; h++) smx[warp * 4 + h] = mx[h];
    }
    __syncthreads();
    if (tid < 4) {
        float m = -1e30f;
#pragma unroll
        for (int w = 0; w < 8; w++) m = fmaxf(m, smx[w * 4 + tid]);
        if (m > -1e29f) atomicMax(&g_gm1u[tid], encf(m));
    }
}

// ---------------- agg1: WARP per node, inline weights, 8-way MLP ----------------
__global__ void __launch_bounds__(256) k_agg1(const float* __restrict__ b1) {
    int warp = threadIdx.x >> 5;
    int n = blockIdx.x * 8 + warp;
    if (n >= NN) return;
    int lane = threadIdx.x & 31;
    int off = g_off[n];
    int deg = g_off[n + 1] - off;
    int hf  = lane >> 3;

    float adh = g_ad1[n * 4 + hf];
    float Bh  = lrelu(decf(g_gm1u[hf]) + adh);

    float acc[8];
#pragma unroll
    for (int q = 0; q < 8; q++) acc[q] = 0.f;
    float wsum = 0.f;

    int j = 0;
    for (; j + 7 < deg; j += 8) {
        int s[8];
#pragma unroll
        for (int u = 0; u < 8; u++) s[u] = g_csr[off + j + u];
        uint4 p[8];
#pragma unroll
        for (int u = 0; u < 8; u++)
            p[u] = __ldcg((const uint4*)&g_h1h[s[u] * 128 + lane * 4]);
        float w[8];
#pragma unroll
        for (int u = 0; u < 8; u++)
            w[u] = __expf(lrelu(g_as1[s[u] * 4 + hf] + adh) - Bh);
#pragma unroll
        for (int u = 0; u < 8; u++) {
            wsum += w[u];
#pragma unroll
            for (int h2i = 0; h2i < 4; h2i++) {
                float2 f = __half22float2(((const __half2*)&p[u])[h2i]);
                acc[2 * h2i]     = fmaf(f.x, w[u], acc[2 * h2i]);
                acc[2 * h2i + 1] = fmaf(f.y, w[u], acc[2 * h2i + 1]);
            }
        }
    }
    for (; j < deg; j++) {
        int s = g_csr[off + j];
        float w = __expf(lrelu(g_as1[s * 4 + hf] + adh) - Bh);
        uint4 p = __ldcg((const uint4*)&g_h1h[s * 128 + lane * 4]);
        wsum += w;
#pragma unroll
        for (int h2i = 0; h2i < 4; h2i++) {
            float2 f = __half22float2(((const __half2*)&p)[h2i]);
            acc[2 * h2i]     = fmaf(f.x, w, acc[2 * h2i]);
            acc[2 * h2i + 1] = fmaf(f.y, w, acc[2 * h2i + 1]);
        }
    }

    float denom = wsum + 1e-16f;
    float4 bb0 = *(const float4*)&b1[lane * 8];
    float4 bb1 = *(const float4*)&b1[lane * 8 + 4];
    float o0 = acc[0] / denom + bb0.x;
    float o1 = acc[1] / denom + bb0.y;
    float o2 = acc[2] / denom + bb0.z;
    float o3 = acc[3] / denom + bb0.w;
    float o4 = acc[4] / denom + bb1.x;
    float o5 = acc[5] / denom + bb1.y;
    float o6 = acc[6] / denom + bb1.z;
    float o7 = acc[7] / denom + bb1.w;
    o0 = (o0 > 0.f) ? o0 : expm1f(o0);
    o1 = (o1 > 0.f) ? o1 : expm1f(o1);
    o2 = (o2 > 0.f) ? o2 : expm1f(o2);
    o3 = (o3 > 0.f) ? o3 : expm1f(o3);
    o4 = (o4 > 0.f) ? o4 : expm1f(o4);
    o5 = (o5 > 0.f) ? o5 : expm1f(o5);
    o6 = (o6 > 0.f) ? o6 : expm1f(o6);
    o7 = (o7 > 0.f) ? o7 : expm1f(o7);
    *(float4*)&g_act[n * C1 + lane * 8]     = make_float4(o0, o1, o2, o3);
    *(float4*)&g_act[n * C1 + lane * 8 + 4] = make_float4(o4, o5, o6, o7);
}

// ---------------- GEMM2 + alpha2 + global-max fused (FFMA2 core) ----------------
__global__ void __launch_bounds__(256) k_gemm2(const float* __restrict__ W2,
                                               const float* __restrict__ av_s,
                                               const float* __restrict__ av_d) {
    __shared__ float sx[C1 * 32];
    __shared__ float sm8[8];
    int m0 = blockIdx.x * 32;
    int tid = threadIdx.x;
    for (int idx = tid; idx < 32 * C1; idx += 256) {
        int i = idx / C1, k = idx % C1;
        sx[k * 32 + i] = (m0 + i < NN) ? g_act[(m0 + i) * C1 + k] : 0.f;
    }
    __syncthreads();
    int col = tid & 31, ir = tid >> 5;
    unsigned long long acc01 = 0ull, acc23 = 0ull;
#pragma unroll 4
    for (int k = 0; k < C1; k++) {
        unsigned long long wd = dup2(W2[k * C2 + col]);
        unsigned long long x01 =
            *reinterpret_cast<const unsigned long long*>(&sx[k * 32 + ir * 4]);
        unsigned long long x23 =
            *reinterpret_cast<const unsigned long long*>(&sx[k * 32 + ir * 4 + 2]);
        acc01 = fma2(x01, wd, acc01);
        acc23 = fma2(x23, wd, acc23);
    }
    float acc[4];
    unpack2(acc01, acc[0], acc[1]);
    unpack2(acc23, acc[2], acc[3]);

    float s_l = av_s[col], d_l = av_d[col];
    float mx = -1e30f;
#pragma unroll
    for (int j = 0; j < 4; j++) {
        int node = m0 + ir * 4 + j;
        if (node < NN) g_h2[node * C2 + col] = acc[j];
        float ss = acc[j] * s_l, sd = acc[j] * d_l;
#pragma unroll
        for (int o = 16; o > 0; o >>= 1) {
            ss += __shfl_down_sync(0xffffffffu, ss, o);
            sd += __shfl_down_sync(0xffffffffu, sd, o);
        }
        if (col == 0 && node < NN) {
            g_as2[node] = ss;
            g_ad2[node] = sd;
            mx = fmaxf(mx, ss);
        }
    }
    if (col == 0) sm8[ir] = mx;
    __syncthreads();
    if (tid == 0) {
        float m = -1e30f;
#pragma unroll
        for (int w = 0; w < 8; w++) m = fmaxf(m, sm8[w]);
        if (m > -1e29f) atomicMax(&g_gm2u, encf(m));
    }
}

// ---------------- agg2: warp per dst node, 8-way MLP ----------------
__global__ void k_agg2(const float* __restrict__ b2, float* __restrict__ out) {
    int warp = threadIdx.x >> 5;
    int n = blockIdx.x * 8 + warp;
    if (n >= NN) return;
    int lane = threadIdx.x & 31;
    int off = g_off[n], deg = g_off[n + 1] - off;
    float adn = g_ad2[n];
    float B = lrelu(decf(g_gm2u) + adn);

    float a[8];
#pragma unroll
    for (int u = 0; u < 8; u++) a[u] = 0.f;
    float ws = 0.f;
    int i = 0;
    for (; i + 7 < deg; i += 8) {
        int s[8];
#pragma unroll
        for (int u = 0; u < 8; u++) s[u] = g_csr[off + i + u];
        float f[8];
#pragma unroll
        for (int u = 0; u < 8; u++) f[u] = __ldcg(&g_h2[s[u] * C2 + lane]);
        float w[8];
#pragma unroll
        for (int u = 0; u < 8; u++) w[u] = __expf(lrelu(g_as2[s[u]] + adn) - B);
#pragma unroll
        for (int u = 0; u < 8; u++) {
            a[u] = fmaf(f[u], w[u], a[u]);
            ws += w[u];
        }
    }
    for (; i < deg; i++) {
        int s = g_csr[off + i];
        float w = __expf(lrelu(g_as2[s] + adn) - B);
        a[0] = fmaf(__ldcg(&g_h2[s * C2 + lane]), w, a[0]);
        ws += w;
    }
    float asum = ((a[0] + a[1]) + (a[2] + a[3])) + ((a[4] + a[5]) + (a[6] + a[7]));
    out[n * C2 + lane] = asum / (ws + 1e-16f) + b2[lane];
}

// ---------------- launch: CSR build (stream 0) ∥ cvtW1+GEMM1 (side stream) ----------------
extern "C" void kernel_launch(void* const* d_in, const int* in_sizes, int n_in,
                              void* d_out, int out_size) {
    const float* x    = (const float*)d_in[0];
    const int*   ei   = (const int*)d_in[1];
    const float* W1   = (const float*)d_in[2];
    const float* as1v = (const float*)d_in[3];
    const float* ad1v = (const float*)d_in[4];
    const float* b1   = (const float*)d_in[5];
    const float* W2   = (const float*)d_in[6];
    const float* as2v = (const float*)d_in[7];
    const float* ad2v = (const float*)d_in[8];
    const float* b2   = (const float*)d_in[9];
    float*       out  = (float*)d_out;

    cudaStream_t s2;
    cudaStreamCreateWithFlags(&s2, cudaStreamNonBlocking);
    cudaEvent_t eRoot, eG1;
    cudaEventCreateWithFlags(&eRoot, cudaEventDisableTiming);
    cudaEventCreateWithFlags(&eG1, cudaEventDisableTiming);

    cudaEventRecord(eRoot, 0);
    cudaStreamWaitEvent(s2, eRoot, 0);
    k_cvtW1<<<(IN * C1 + 255) / 256, 256, 0, s2>>>(W1);
    k_gemm1<<<(NN + 31) / 32, 256, 0, s2>>>(x, as1v, ad1v);
    cudaEventRecord(eG1, s2);

    // CSR chain on the main stream (3-kernel scan, as in the 252.7us baseline)
    k_zero_deg<<<(NN + 255) / 256, 256>>>(ei);
    k_count<<<(ETOT + 255) / 256, 256>>>(ei);
    k_scan_local<<<NB, SCAN_B>>>();
    k_scan_bsum<<<1, 128>>>();
    k_scan_add<<<NB, SCAN_B>>>();
    k_fill<<<(ETOT + 255) / 256, 256>>>(ei);

    // join, then the dependent chain
    cudaStreamWaitEvent(0, eG1, 0);
    k_agg1<<<(NN + 7) / 8, 256>>>(b1);
    k_gemm2<<<(NN + 31) / 32, 256>>>(W2, as2v, ad2v);
    k_agg2<<<(NN + 7) / 8, 256>>>(b2, out);
    // s2 / events intentionally leaked (host handles only)
}